// round 10
// baseline (speedup 1.0000x reference)
#include <cuda_runtime.h>

// FFM pairwise interactions:
//   inputs: (B=4096, 400, 64) fp32, v[b, j, i, e]
//   output: (B, 1, 190, 64) fp32, out[b,0,p,:] = v[b,jj,ii,:] * v[b,ii,jj,:]
// Pure HBM streaming at the 597 MB algorithmic floor; pinned at ~86% DRAM.
// R7: same v8(.cs) + ILP=2 as R6, but BLOCK-stride instead of grid-stride so
// each block's read+write footprint is one contiguous window (long DRAM bursts,
// same-page paired reads) instead of two windows ~300 MB apart.

constexpr int N_FIELDS = 20;
constexpr int NPAIRS   = 190;
constexpr int ROW_FLT  = N_FIELDS * N_FIELDS * 64;   // 25600 floats per batch
constexpr int TOTAL_F8 = 4096 * NPAIRS * 8;          // 6,220,800 32-B chunks
constexpr int ILP      = 2;
constexpr int THREADS  = 256;
constexpr int BLOCKS   = TOTAL_F8 / (THREADS * ILP); // 12150 exact

// Per-pair row offsets in floats: offA[p] = (j*20+i)*64, offC[p] = (i*20+j)*64
struct PairTab { int offA[NPAIRS]; int offC[NPAIRS]; };
constexpr PairTab make_tab() {
    PairTab t{};
    int p = 0;
    for (int i = 0; i < N_FIELDS; ++i)
        for (int j = i + 1; j < N_FIELDS; ++j, ++p) {
            t.offA[p] = (j * N_FIELDS + i) * 64;
            t.offC[p] = (i * N_FIELDS + j) * 64;
        }
    return t;
}
__constant__ PairTab TAB = make_tab();

__device__ __forceinline__ void ld256cs(const float* p, float* r) {
    asm volatile("ld.global.cs.v8.f32 {%0,%1,%2,%3,%4,%5,%6,%7}, [%8];"
        : "=f"(r[0]), "=f"(r[1]), "=f"(r[2]), "=f"(r[3]),
          "=f"(r[4]), "=f"(r[5]), "=f"(r[6]), "=f"(r[7])
        : "l"(p));
}

__device__ __forceinline__ void st256cs(float* p, const float* r) {
    asm volatile("st.global.cs.v8.f32 [%0], {%1,%2,%3,%4,%5,%6,%7,%8};"
        :: "l"(p),
           "f"(r[0]), "f"(r[1]), "f"(r[2]), "f"(r[3]),
           "f"(r[4]), "f"(r[5]), "f"(r[6]), "f"(r[7])
        : "memory");
}

__global__ void __launch_bounds__(THREADS)
ffm_pair_kernel(const float* __restrict__ in, float* __restrict__ out)
{
    // Block-stride: block owns a contiguous span of ILP*THREADS chunks (16 KB out).
    const int base_f8 = blockIdx.x * (THREADS * ILP) + threadIdx.x;

    int          f8i[ILP];
    const float* pa[ILP];
    const float* pc[ILP];

    // Address generation first (ALU/LDC only), then batch the 4 loads.
    #pragma unroll
    for (int k = 0; k < ILP; ++k) {
        int f8 = base_f8 + k * THREADS;   // exact grid: always < TOTAL_F8
        f8i[k] = f8;
        int q8 = f8 & 7;                  // 32-B chunk within the 256-B row
        int bp = f8 >> 3;                 // b * NPAIRS + p
        int p  = bp % NPAIRS;             // magic-mul
        int b  = bp / NPAIRS;
        const float* base = in + (long)b * ROW_FLT + q8 * 8;
        pa[k] = base + TAB.offA[p];
        pc[k] = base + TAB.offC[p];
    }

    // 4 independent 256-bit loads in flight, all within one batch window.
    float a[ILP][8], c[ILP][8];
    #pragma unroll
    for (int k = 0; k < ILP; ++k) ld256cs(pa[k], a[k]);
    #pragma unroll
    for (int k = 0; k < ILP; ++k) ld256cs(pc[k], c[k]);

    #pragma unroll
    for (int k = 0; k < ILP; ++k) {
        float r[8];
        #pragma unroll
        for (int e = 0; e < 8; ++e) r[e] = a[k][e] * c[k][e];
        st256cs(out + (long)f8i[k] * 8, r);
    }
}

extern "C" void kernel_launch(void* const* d_in, const int* in_sizes, int n_in,
                              void* d_out, int out_size)
{
    const float* in  = (const float*)d_in[0];
    float*       out = (float*)d_out;
    ffm_pair_kernel<<<BLOCKS, THREADS>>>(in, out);
}

// round 12
// speedup vs baseline: 1.0294x; 1.0294x over previous
#include <cuda_runtime.h>

// FFM pairwise interactions:
//   inputs: (B=4096, 400, 64) fp32, v[b, j, i, e]
//   output: (B, 1, 190, 64) fp32, out[b,0,p,:] = v[b,jj,ii,:] * v[b,ii,jj,:]
//
// Converged HBM-streaming kernel. Findings across R1-R7:
//   - traffic is at the algorithmic floor (597 MB: 380/400 input rows read
//     once each, output written once; zero reuse anywhere)
//   - DRAM pins at 85.6-86.0% (~6.8 TB/s) for every structural variant
//     (ILP 1/2/4, float4 vs v8.f32, grid- vs block-stride) => chip ceiling
//     for a 2:1 read/write mixed stream
//   - wall-clock favored the simplest one-float4-per-thread mapping (R1)
// R10: R1 mapping + constant-table pair decode + .cs streaming hints.

constexpr int N_FIELDS = 20;
constexpr int NPAIRS   = 190;
constexpr int QUADS    = 16;                           // float4 per 64-elem row
constexpr int ROW_F4   = N_FIELDS * N_FIELDS * QUADS;  // 6400 float4 per batch
constexpr int TOTAL_F4 = 4096 * NPAIRS * QUADS;        // 12,441,600
constexpr int THREADS  = 256;
constexpr int BLOCKS   = TOTAL_F4 / THREADS;           // 48600 exact

// Per-pair float4 offsets: offA[p] = (j*20+i)*16, offC[p] = (i*20+j)*16
struct PairTab { unsigned short offA[NPAIRS]; unsigned short offC[NPAIRS]; };
constexpr PairTab make_tab() {
    PairTab t{};
    int p = 0;
    for (int i = 0; i < N_FIELDS; ++i)
        for (int j = i + 1; j < N_FIELDS; ++j, ++p) {
            t.offA[p] = (unsigned short)((j * N_FIELDS + i) * QUADS);
            t.offC[p] = (unsigned short)((i * N_FIELDS + j) * QUADS);
        }
    return t;
}
__constant__ PairTab TAB = make_tab();

__global__ void __launch_bounds__(THREADS)
ffm_pair_kernel(const float4* __restrict__ in, float4* __restrict__ out)
{
    int f4 = blockIdx.x * THREADS + threadIdx.x;   // output float4 index (exact grid)

    int q  = f4 & (QUADS - 1);    // quad within the 256-B pair row
    int bp = f4 >> 4;             // b * NPAIRS + p
    int p  = bp % NPAIRS;         // magic-mul
    int b  = bp / NPAIRS;

    const float4* base = in + (long)b * ROW_F4 + q;
    float4 a = __ldcs(base + TAB.offA[p]);   // v[b, j, i, :] streaming load
    float4 c = __ldcs(base + TAB.offC[p]);   // v[b, i, j, :]

    float4 r;
    r.x = a.x * c.x;
    r.y = a.y * c.y;
    r.z = a.z * c.z;
    r.w = a.w * c.w;

    __stcs(&out[f4], r);                     // streaming store
}

extern "C" void kernel_launch(void* const* d_in, const int* in_sizes, int n_in,
                              void* d_out, int out_size)
{
    const float4* in  = (const float4*)d_in[0];
    float4*       out = (float4*)d_out;
    ffm_pair_kernel<<<BLOCKS, THREADS>>>(in, out);
}